// round 10
// baseline (speedup 1.0000x reference)
#include <cuda_runtime.h>
#include <math.h>

// ---------------------------------------------------------------------------
// BSLoss fused single-kernel (v5b): occupancy push (resubmit after infra flake).
//  - 4 cols/thread (1x float4 rolling), ~40 regs -> 6 CTAs/SM (75% occ cap)
//  - grid 4x222 = 888 CTAs = 148 SMs x 6, single balanced wave
//  - no prefetch (regressed in v4); SMEM per-row coefficients; dual accums
//  - hoisted halo base pointers out of the inner loop
// total = pde_sum/n_int + 10*bc_sum/N_T + 10*tc_sum/N_S
// ---------------------------------------------------------------------------

#define NS 4096
#define NT 4096
#define ROWF 4096
#define GRIDY 222
#define NBLK (4 * GRIDY)
#define STRIP 19

#define INV4095   (1.0f / 4095.0f)
#define INV2DU    2047.5f
#define INVDU2    16769025.0f
#define INV2DT    102375.0f
#define ALPHA_C   2.5f

__device__ float4 g_part[NBLK];           // .x=pde .y=bc .z=tc
__device__ unsigned int g_count;          // zero-init; self-wraps each replay

// cf.x = INVDU2/Sun^2 ; cf.y = INV2DU*Suun/Sun^3 ; cf.z = Sn^2 ; cf.w = ALPHA*Sn*INV2DU/Sun
__device__ __forceinline__ float pde_pt(float vm, float vc, float vp,
                                        float vtl, float vtr, float4 cf,
                                        float acc) {
    float du  = vp - vm;
    float uu  = fmaf(-2.0f, vc, vp + vm);
    float dt  = vtr - vtl;
    float vss = fmaf(uu, cf.x, -du * cf.y);
    vss = fminf(100.0f, fmaxf(-100.0f, vss));
    float r = fmaf(INV2DT, dt, ALPHA_C * vc);
    r = fmaf(-cf.w, du, r);
    r = fmaf(-cf.z, vss, r);
    return fmaf(r, r, acc);
}

__global__ void __launch_bounds__(256, 6)
k_fused(const float* __restrict__ V, float* __restrict__ out,
        float C1f, float C2f) {
    const int tid  = threadIdx.x;
    const int lane = tid & 31;
    const int wid  = tid >> 5;
    const int bid  = blockIdx.y * gridDim.x + blockIdx.x;

    const int j4 = (blockIdx.x * 256 + tid) * 4;            // grid.x = 4
    const int s0 = 1 + blockIdx.y * STRIP;                  // grid.y = 222
    const int send = min(s0 + STRIP, NS - 1);               // exclusive

    __shared__ float4 sCoef[STRIP];
    __shared__ float ws[8][3];
    __shared__ bool is_last;

    // ---- per-row coefficients (one thread per row) ----
    if (tid < STRIP) {
        const float dL = C2f - C1f;
        float u    = (float)(s0 + tid) * INV4095;
        float L    = fmaf(dL, u, C1f);
        float L2   = L * L;
        float S    = fmaf(30.0f, fmaf(L2 * L, (1.0f / 6.0f), L), 100.0f);
        float dS   = 30.0f * dL * fmaf(0.5f, L2, 1.0f);
        float d2S  = 30.0f * dL * dL * L;
        float Sn   = S   * (1.0f / 300.0f);
        float Sun  = dS  * (1.0f / 300.0f);
        float Suun = d2S * (1.0f / 300.0f);
        float inv  = __fdividef(1.0f, Sun);
        float inv2 = inv * inv;
        float inv3 = inv2 * inv;
        sCoef[tid] = make_float4(INVDU2 * inv2,
                                 INV2DU * Suun * inv3,
                                 Sn * Sn,
                                 ALPHA_C * Sn * INV2DU * inv);
    }
    __syncthreads();

    float facc0 = 0.0f, facc1 = 0.0f;

    if (s0 < NS - 1) {
        const float mk0 = (j4 > 0) ? 1.0f : 0.0f;           // j=0 excluded
        const float mk3 = (j4 + 3 <= NT - 2) ? 1.0f : 0.0f; // j=NT-1 excluded
        const float* col = V + j4;

        // hoisted halo pointers (valid offset even when predicated off)
        const bool  eL = (lane == 0)  && (j4 > 0);
        const bool  eR = (lane == 31) && (j4 + 4 < NT);
        const float* haloL = col + (size_t)s0 * ROWF - 1;   // advances by ROWF per row
        const float* haloR = col + (size_t)s0 * ROWF + 4;

        float4 m = *reinterpret_cast<const float4*>(col + (size_t)(s0 - 1) * ROWF);
        float4 c = *reinterpret_cast<const float4*>(col + (size_t)s0 * ROWF);

        #pragma unroll 1
        for (int s = s0; s < send; ++s) {
            float4 p = *reinterpret_cast<const float4*>(col + (size_t)(s + 1) * ROWF);

            float l = __shfl_up_sync(0xffffffffu, c.w, 1);
            float r = __shfl_down_sync(0xffffffffu, c.x, 1);
            if (eL) l = *haloL;
            if (eR) r = *haloR;
            haloL += ROWF; haloR += ROWF;

            float4 cf = sCoef[s - s0];   // broadcast LDS.128

            float f0 = pde_pt(m.x, c.x, p.x, l,   c.y, cf, 0.0f);
            facc0 = fmaf(mk0, f0, facc0);
            facc1 = pde_pt(m.y, c.y, p.y, c.x, c.z, cf, facc1);
            facc0 = pde_pt(m.z, c.z, p.z, c.y, c.w, cf, facc0);
            float f3 = pde_pt(m.w, c.w, p.w, c.z, r,   cf, 0.0f);
            facc1 = fmaf(mk3, f3, facc1);

            m = c; c = p;
        }
    }
    float facc = facc0 + facc1;

    // ---- boundary terms on the 4 blocks of strip 0 (1024 threads x 4 elems) ----
    float bacc = 0.0f, tacc = 0.0f;
    if (blockIdx.y == 0) {
        int base = (blockIdx.x * 256 + tid) * 4;
        #pragma unroll
        for (int k = 0; k < 4; ++k) {
            int idx = base + k;
            float g  = (float)idx * INV4095;
            float vb  = V[(size_t)(NS - 1) * ROWF + idx];
            float tgt = 1.0f - (100.0f / 300.0f) * expf(-0.05f * (1.0f - g));
            float db  = vb - tgt;
            bacc += db * db;
            float vt = V[(size_t)idx * ROWF + (NT - 1)];
            float x  = 50.0f * (g - (100.0f / 300.0f));
            float sp = fmaxf(x, 0.0f) + log1pf(expf(-fabsf(x)));
            float d  = vt - sp * 0.02f;
            float ad = fabsf(d);
            tacc += (ad < 0.01f) ? 0.5f * d * d : 0.01f * (ad - 0.005f);
        }
    }

    // ---- block reduce (3 values) ----
    #pragma unroll
    for (int o = 16; o; o >>= 1) {
        facc += __shfl_xor_sync(0xffffffffu, facc, o);
        bacc += __shfl_xor_sync(0xffffffffu, bacc, o);
        tacc += __shfl_xor_sync(0xffffffffu, tacc, o);
    }
    if (lane == 0) { ws[wid][0] = facc; ws[wid][1] = bacc; ws[wid][2] = tacc; }
    __syncthreads();
    if (tid == 0) {
        float p = 0.f, b = 0.f, t = 0.f;
        #pragma unroll
        for (int i = 0; i < 8; ++i) { p += ws[i][0]; b += ws[i][1]; t += ws[i][2]; }
        g_part[bid] = make_float4(p, b, t, 0.0f);
        __threadfence();
        unsigned prev = atomicInc(&g_count, NBLK - 1);
        is_last = (prev == NBLK - 1);
    }
    __syncthreads();

    // ---- last block: final reduction in double + scalar output ----
    if (is_last) {
        __threadfence();
        double p = 0.0, b = 0.0, t = 0.0;
        for (int i = tid; i < NBLK; i += 256) {
            float4 v = g_part[i];
            p += (double)v.x; b += (double)v.y; t += (double)v.z;
        }
        #pragma unroll
        for (int o = 16; o; o >>= 1) {
            p += __shfl_xor_sync(0xffffffffu, p, o);
            b += __shfl_xor_sync(0xffffffffu, b, o);
            t += __shfl_xor_sync(0xffffffffu, t, o);
        }
        __shared__ double ds[8][3];
        if (lane == 0) { ds[wid][0] = p; ds[wid][1] = b; ds[wid][2] = t; }
        __syncthreads();
        if (tid == 0) {
            double P = 0.0, Bv = 0.0, T = 0.0;
            #pragma unroll
            for (int i = 0; i < 8; ++i) { P += ds[i][0]; Bv += ds[i][1]; T += ds[i][2]; }
            const double n_int = (double)(NS - 2) * (double)(NT - 2);
            out[0] = (float)(P / n_int + 10.0 * (Bv / (double)NT) + 10.0 * (T / (double)NS));
        }
    }
}

// host-side cubic root (CubicStretching), double precision
static double solve_depressed_cubic(double Q) {
    const double p = 6.0;
    double q = 6.0 * Q;
    double sp = sqrt(p);
    double arg = fabs(q) / (2.0 * p * sp / (3.0 * sqrt(3.0)));
    if (arg < 1.0) arg = 1.0;
    double c = 2.0 * sp * cosh(acosh(arg) / 3.0);
    return (q >= 0.0) ? -c : c;
}

extern "C" void kernel_launch(void* const* d_in, const int* in_sizes, int n_in,
                              void* d_out, int out_size) {
    const float* V = (const float*)d_in[0];
    float* out = (float*)d_out;

    double C1 = solve_depressed_cubic((100.0 - 0.0)   / 30.0);
    double C2 = solve_depressed_cubic((100.0 - 300.0) / 30.0);

    dim3 grid(4, GRIDY);   // 888 blocks = 148 SMs * 6 CTAs, single balanced wave
    k_fused<<<grid, 256>>>(V, out, (float)C1, (float)C2);
}

// round 11
// speedup vs baseline: 1.5648x; 1.5648x over previous
#include <cuda_runtime.h>
#include <math.h>

// ---------------------------------------------------------------------------
// BSLoss fused single-kernel (v6): latency coverage via 2-rows-per-iteration.
//  - 8 cols/thread, 2 rows/iter -> 4 independent LDG.128 batched per iter
//  - grid 2x293 = 586 CTAs ~ 148 SMs x 4 slots, single wave; STRIP=14 (even)
//  - SMEM per-row coefficients; 4 accumulators
// total = pde_sum/n_int + 10*bc_sum/N_T + 10*tc_sum/N_S
// ---------------------------------------------------------------------------

#define NS 4096
#define NT 4096
#define ROWF 4096
#define GRIDY 293
#define NBLK (2 * GRIDY)
#define STRIP 14

#define INV4095   (1.0f / 4095.0f)
#define INV2DU    2047.5f
#define INVDU2    16769025.0f
#define INV2DT    102375.0f
#define ALPHA_C   2.5f

__device__ float4 g_part[NBLK];           // .x=pde .y=bc .z=tc
__device__ unsigned int g_count;          // zero-init; self-wraps each replay

// cf.x = INVDU2/Sun^2 ; cf.y = INV2DU*Suun/Sun^3 ; cf.z = Sn^2 ; cf.w = ALPHA*Sn*INV2DU/Sun
__device__ __forceinline__ float pde_pt(float vm, float vc, float vp,
                                        float vtl, float vtr, float4 cf,
                                        float acc) {
    float du  = vp - vm;
    float uu  = fmaf(-2.0f, vc, vp + vm);
    float dt  = vtr - vtl;
    float vss = fmaf(uu, cf.x, -du * cf.y);
    vss = fminf(100.0f, fmaxf(-100.0f, vss));
    float r = fmaf(INV2DT, dt, ALPHA_C * vc);
    r = fmaf(-cf.w, du, r);
    r = fmaf(-cf.z, vss, r);
    return fmaf(r, r, acc);
}

__global__ void __launch_bounds__(256, 4)
k_fused(const float* __restrict__ V, float* __restrict__ out,
        float C1f, float C2f) {
    const int tid  = threadIdx.x;
    const int lane = tid & 31;
    const int wid  = tid >> 5;
    const int bid  = blockIdx.y * gridDim.x + blockIdx.x;

    const int j8 = (blockIdx.x * 256 + tid) * 8;            // grid.x = 2
    const int s0 = 1 + blockIdx.y * STRIP;                  // grid.y = 293
    const int send = min(s0 + STRIP, NS - 1);               // exclusive; (send-s0) even

    __shared__ float4 sCoef[STRIP];
    __shared__ float ws[8][3];
    __shared__ bool is_last;

    // ---- per-row coefficients (one thread per row) ----
    if (tid < STRIP) {
        const float dL = C2f - C1f;
        float u    = (float)(s0 + tid) * INV4095;
        float L    = fmaf(dL, u, C1f);
        float L2   = L * L;
        float S    = fmaf(30.0f, fmaf(L2 * L, (1.0f / 6.0f), L), 100.0f);
        float dS   = 30.0f * dL * fmaf(0.5f, L2, 1.0f);
        float d2S  = 30.0f * dL * dL * L;
        float Sn   = S   * (1.0f / 300.0f);
        float Sun  = dS  * (1.0f / 300.0f);
        float Suun = d2S * (1.0f / 300.0f);
        float inv  = __fdividef(1.0f, Sun);
        float inv2 = inv * inv;
        float inv3 = inv2 * inv;
        sCoef[tid] = make_float4(INVDU2 * inv2,
                                 INV2DU * Suun * inv3,
                                 Sn * Sn,
                                 ALPHA_C * Sn * INV2DU * inv);
    }
    __syncthreads();

    float facc0 = 0.0f, facc1 = 0.0f, facc2 = 0.0f, facc3 = 0.0f;

    if (s0 < NS - 1) {
        const float mk0 = (j8 > 0) ? 1.0f : 0.0f;           // j=0 excluded
        const float mk7 = (j8 + 7 <= NT - 2) ? 1.0f : 0.0f; // j=NT-1 excluded
        const float* col = V + j8;

        float4 m0 = *reinterpret_cast<const float4*>(col + (size_t)(s0 - 1) * ROWF);
        float4 m1 = *reinterpret_cast<const float4*>(col + (size_t)(s0 - 1) * ROWF + 4);
        float4 c0 = *reinterpret_cast<const float4*>(col + (size_t)s0 * ROWF);
        float4 c1 = *reinterpret_cast<const float4*>(col + (size_t)s0 * ROWF + 4);

        #pragma unroll 1
        for (int s = s0; s < send; s += 2) {
            // 4 independent LDG.128 batched up front (rows s+1, s+2)
            const float* rp = col + (size_t)(s + 1) * ROWF;
            const float* rq = col + (size_t)(s + 2) * ROWF;
            float4 p0 = *reinterpret_cast<const float4*>(rp);
            float4 p1 = *reinterpret_cast<const float4*>(rp + 4);
            float4 q0 = *reinterpret_cast<const float4*>(rq);
            float4 q1 = *reinterpret_cast<const float4*>(rq + 4);

            // ---- row s  (m, c, p) ----
            float l = __shfl_up_sync(0xffffffffu, c1.w, 1);
            float r = __shfl_down_sync(0xffffffffu, c0.x, 1);
            if (lane == 0)  l = (j8 > 0)      ? col[(size_t)s * ROWF - 1] : 0.0f;
            if (lane == 31) r = (j8 + 8 < NT) ? col[(size_t)s * ROWF + 8] : 0.0f;
            float4 cf = sCoef[s - s0];

            float f0 = pde_pt(m0.x, c0.x, p0.x, l,    c0.y, cf, 0.0f);
            facc0 = fmaf(mk0, f0, facc0);
            facc1 = pde_pt(m0.y, c0.y, p0.y, c0.x, c0.z, cf, facc1);
            facc2 = pde_pt(m0.z, c0.z, p0.z, c0.y, c0.w, cf, facc2);
            facc3 = pde_pt(m0.w, c0.w, p0.w, c0.z, c1.x, cf, facc3);
            facc0 = pde_pt(m1.x, c1.x, p1.x, c0.w, c1.y, cf, facc0);
            facc1 = pde_pt(m1.y, c1.y, p1.y, c1.x, c1.z, cf, facc1);
            facc2 = pde_pt(m1.z, c1.z, p1.z, c1.y, c1.w, cf, facc2);
            float f7 = pde_pt(m1.w, c1.w, p1.w, c1.z, r,    cf, 0.0f);
            facc3 = fmaf(mk7, f7, facc3);

            // ---- row s+1  (c, p, q) ----
            float l2 = __shfl_up_sync(0xffffffffu, p1.w, 1);
            float r2 = __shfl_down_sync(0xffffffffu, p0.x, 1);
            if (lane == 0)  l2 = (j8 > 0)      ? rp[-1] : 0.0f;
            if (lane == 31) r2 = (j8 + 8 < NT) ? rp[8]  : 0.0f;
            float4 cg = sCoef[s - s0 + 1];

            float g0 = pde_pt(c0.x, p0.x, q0.x, l2,   p0.y, cg, 0.0f);
            facc0 = fmaf(mk0, g0, facc0);
            facc1 = pde_pt(c0.y, p0.y, q0.y, p0.x, p0.z, cg, facc1);
            facc2 = pde_pt(c0.z, p0.z, q0.z, p0.y, p0.w, cg, facc2);
            facc3 = pde_pt(c0.w, p0.w, q0.w, p0.z, p1.x, cg, facc3);
            facc0 = pde_pt(c1.x, p1.x, q1.x, p0.w, p1.y, cg, facc0);
            facc1 = pde_pt(c1.y, p1.y, q1.y, p1.x, p1.z, cg, facc1);
            facc2 = pde_pt(c1.z, p1.z, q1.z, p1.y, p1.w, cg, facc2);
            float g7 = pde_pt(c1.w, p1.w, q1.w, p1.z, r2,   cg, 0.0f);
            facc3 = fmaf(mk7, g7, facc3);

            m0 = p0; m1 = p1; c0 = q0; c1 = q1;
        }
    }
    float facc = (facc0 + facc1) + (facc2 + facc3);

    // ---- boundary terms on the 2 blocks of strip 0 (512 threads x 8 elems) ----
    float bacc = 0.0f, tacc = 0.0f;
    if (blockIdx.y == 0) {
        int base = (blockIdx.x * 256 + tid) * 8;
        #pragma unroll
        for (int k = 0; k < 8; ++k) {
            int idx = base + k;
            float g  = (float)idx * INV4095;
            float vb  = V[(size_t)(NS - 1) * ROWF + idx];
            float tgt = 1.0f - (100.0f / 300.0f) * expf(-0.05f * (1.0f - g));
            float db  = vb - tgt;
            bacc += db * db;
            float vt = V[(size_t)idx * ROWF + (NT - 1)];
            float x  = 50.0f * (g - (100.0f / 300.0f));
            float sp = fmaxf(x, 0.0f) + log1pf(expf(-fabsf(x)));
            float d  = vt - sp * 0.02f;
            float ad = fabsf(d);
            tacc += (ad < 0.01f) ? 0.5f * d * d : 0.01f * (ad - 0.005f);
        }
    }

    // ---- block reduce (3 values) ----
    #pragma unroll
    for (int o = 16; o; o >>= 1) {
        facc += __shfl_xor_sync(0xffffffffu, facc, o);
        bacc += __shfl_xor_sync(0xffffffffu, bacc, o);
        tacc += __shfl_xor_sync(0xffffffffu, tacc, o);
    }
    if (lane == 0) { ws[wid][0] = facc; ws[wid][1] = bacc; ws[wid][2] = tacc; }
    __syncthreads();
    if (tid == 0) {
        float p = 0.f, b = 0.f, t = 0.f;
        #pragma unroll
        for (int i = 0; i < 8; ++i) { p += ws[i][0]; b += ws[i][1]; t += ws[i][2]; }
        g_part[bid] = make_float4(p, b, t, 0.0f);
        __threadfence();
        unsigned prev = atomicInc(&g_count, NBLK - 1);
        is_last = (prev == NBLK - 1);
    }
    __syncthreads();

    // ---- last block: final reduction in double + scalar output ----
    if (is_last) {
        __threadfence();
        double p = 0.0, b = 0.0, t = 0.0;
        for (int i = tid; i < NBLK; i += 256) {
            float4 v = g_part[i];
            p += (double)v.x; b += (double)v.y; t += (double)v.z;
        }
        #pragma unroll
        for (int o = 16; o; o >>= 1) {
            p += __shfl_xor_sync(0xffffffffu, p, o);
            b += __shfl_xor_sync(0xffffffffu, b, o);
            t += __shfl_xor_sync(0xffffffffu, t, o);
        }
        __shared__ double ds[8][3];
        if (lane == 0) { ds[wid][0] = p; ds[wid][1] = b; ds[wid][2] = t; }
        __syncthreads();
        if (tid == 0) {
            double P = 0.0, Bv = 0.0, T = 0.0;
            #pragma unroll
            for (int i = 0; i < 8; ++i) { P += ds[i][0]; Bv += ds[i][1]; T += ds[i][2]; }
            const double n_int = (double)(NS - 2) * (double)(NT - 2);
            out[0] = (float)(P / n_int + 10.0 * (Bv / (double)NT) + 10.0 * (T / (double)NS));
        }
    }
}

// host-side cubic root (CubicStretching), double precision
static double solve_depressed_cubic(double Q) {
    const double p = 6.0;
    double q = 6.0 * Q;
    double sp = sqrt(p);
    double arg = fabs(q) / (2.0 * p * sp / (3.0 * sqrt(3.0)));
    if (arg < 1.0) arg = 1.0;
    double c = 2.0 * sp * cosh(acosh(arg) / 3.0);
    return (q >= 0.0) ? -c : c;
}

extern "C" void kernel_launch(void* const* d_in, const int* in_sizes, int n_in,
                              void* d_out, int out_size) {
    const float* V = (const float*)d_in[0];
    float* out = (float*)d_out;

    double C1 = solve_depressed_cubic((100.0 - 0.0)   / 30.0);
    double C2 = solve_depressed_cubic((100.0 - 300.0) / 30.0);

    dim3 grid(2, GRIDY);   // 586 blocks ~ 148 SMs x 4 slots, single wave
    k_fused<<<grid, 256>>>(V, out, (float)C1, (float)C2);
}